// round 3
// baseline (speedup 1.0000x reference)
#include <cuda_runtime.h>
#include <cstddef>

#define N_NODES 50000
#define D_H 128
#define D_OUT 64
#define MAX_E 800000
#define EPS 1e-5f

typedef unsigned long long ull;

// ---------------- scratch ---------------------------------------------------
__device__ float g_bufA[(size_t)N_NODES * D_H];
__device__ float g_bufB[(size_t)N_NODES * D_H];
__device__ float g_bufC[(size_t)N_NODES * D_OUT];
__device__ float g_dinv[N_NODES];
__device__ int   g_cnt[N_NODES];
__device__ int   g_cur[N_NODES];
__device__ int   g_off[N_NODES + 1];
__device__ int   g_col[MAX_E];
__device__ int   g_bsum[64];
__device__ int   g_nz;   // nonzero hi-words seen -> indices are int32

// ---------------- preprocessing ---------------------------------------------
__global__ void k_init_detect(const int* __restrict__ p) {
    int i = blockIdx.x * blockDim.x + threadIdx.x;
    if (i < N_NODES) { g_cnt[i] = 0; g_cur[i] = 0; }
    if (i == 0) g_nz = 0;
    // dtype sniff: int64 indices < 50000 have zero hi-words (little endian)
    if (i < 1024) {
        if (p[2 * i + 1] != 0) atomicOr(&g_nz, 1);
    }
}

__device__ __forceinline__ int load_idx(const void* p, long long i, int is64) {
    return is64 ? (int)((const long long*)p)[i] : ((const int*)p)[i];
}

__global__ void k_degree(const void* __restrict__ idx, int E) {
    int e = blockIdx.x * blockDim.x + threadIdx.x;
    if (e >= E) return;
    int is64 = (g_nz == 0);
    int d = load_idx(idx, (long long)E + e, is64);
    atomicAdd(&g_cnt[d], 1);
}

__global__ void k_scanA() {
    __shared__ int s[1024];
    int i = blockIdx.x * 1024 + threadIdx.x;
    s[threadIdx.x] = (i < N_NODES) ? g_cnt[i] : 0;
    __syncthreads();
    for (int d = 512; d > 0; d >>= 1) {
        if (threadIdx.x < d) s[threadIdx.x] += s[threadIdx.x + d];
        __syncthreads();
    }
    if (threadIdx.x == 0) g_bsum[blockIdx.x] = s[0];
}

__global__ void k_scanB(int nb) {
    if (threadIdx.x == 0) {
        int run = 0;
        for (int b = 0; b < nb; b++) { int t = g_bsum[b]; g_bsum[b] = run; run += t; }
        g_off[N_NODES] = run;
    }
}

__global__ void k_scanC() {
    __shared__ int s[1024];
    int t = threadIdx.x;
    int i = blockIdx.x * 1024 + t;
    int v = (i < N_NODES) ? g_cnt[i] : 0;
    s[t] = v;
    __syncthreads();
    for (int d = 1; d < 1024; d <<= 1) {
        int x = (t >= d) ? s[t - d] : 0;
        __syncthreads();
        s[t] += x;
        __syncthreads();
    }
    if (i < N_NODES) {
        g_off[i] = g_bsum[blockIdx.x] + s[t] - v;  // exclusive
        g_dinv[i] = rsqrtf((float)v + 1.0f);       // +1 self loop
    }
}

__global__ void k_fill(const void* __restrict__ idx, int E) {
    int e = blockIdx.x * blockDim.x + threadIdx.x;
    if (e >= E) return;
    int is64 = (g_nz == 0);
    int s = load_idx(idx, e, is64);
    int d = load_idx(idx, (long long)E + e, is64);
    int pos = atomicAdd(&g_cur[d], 1);
    g_col[g_off[d] + pos] = s;
}

// ---------------- packed f32x2 helpers --------------------------------------
__device__ __forceinline__ ull pack_dup(float a) {
    ull r;
    asm("mov.b64 %0, {%1, %1};" : "=l"(r) : "f"(a));
    return r;
}
__device__ __forceinline__ ull ffma2(ull a, ull b, ull c) {
    ull d;
    asm("fma.rn.f32x2 %0, %1, %2, %3;" : "=l"(d) : "l"(a), "l"(b), "l"(c));
    return d;
}

// ---------------- SGEMM: C[M,BN] = A[M,128] @ W[128,BN] ---------------------
// 128xBN tile, TM=TN=8 per thread, packed FFMA2 accumulators.
template <int BN>
__global__ void k_gemm(const float* __restrict__ A, const float* __restrict__ W,
                       float* __restrict__ C) {
    constexpr int BM = 128, BK = 16, TM = 8, TN = 8;
    constexpr int TX = BN / TN;   // 16 (BN=128) or 8 (BN=64)
    constexpr int TY = BM / TM;   // 16
    constexpr int NT = TX * TY;   // 256 or 128
    __shared__ float As[BM][BK];  // row-major: float4 reads along k
    __shared__ float Ws[BK][BN];

    int tid = threadIdx.x;
    int tx = tid % TX, ty = tid / TX;
    int rowBase = blockIdx.x * BM;

    ull acc[TM][TN / 2];
#pragma unroll
    for (int i = 0; i < TM; i++)
#pragma unroll
        for (int j = 0; j < TN / 2; j++) acc[i][j] = 0ull;

    for (int k0 = 0; k0 < 128; k0 += BK) {
        // load A tile: BM*BK/4 float4 slots
#pragma unroll
        for (int li = tid; li < BM * BK / 4; li += NT) {
            int m = li / (BK / 4);
            int q = li % (BK / 4);
            int gr = rowBase + m;
            float4 v = make_float4(0.f, 0.f, 0.f, 0.f);
            if (gr < N_NODES) v = *(const float4*)&A[(size_t)gr * 128 + k0 + 4 * q];
            *(float4*)&As[m][4 * q] = v;
        }
        // load W tile
#pragma unroll
        for (int li = tid; li < BK * BN / 4; li += NT) {
            int kk = li / (BN / 4);
            int c = li % (BN / 4);
            *(float4*)&Ws[kk][4 * c] = *(const float4*)&W[(size_t)(k0 + kk) * BN + 4 * c];
        }
        __syncthreads();

#pragma unroll
        for (int kk4 = 0; kk4 < BK; kk4 += 4) {
            float4 aF[TM];
#pragma unroll
            for (int i = 0; i < TM; i++) aF[i] = *(const float4*)&As[ty * TM + i][kk4];
#pragma unroll
            for (int j = 0; j < 4; j++) {
                int kk = kk4 + j;
                // b: TN consecutive cols as TN/2 packed pairs
                float4 b0 = *(const float4*)&Ws[kk][tx * TN];
                float4 b1 = *(const float4*)&Ws[kk][tx * TN + 4];
                ull bp[TN / 2];
                bp[0] = ((const ull*)&b0)[0];
                bp[1] = ((const ull*)&b0)[1];
                bp[2] = ((const ull*)&b1)[0];
                bp[3] = ((const ull*)&b1)[1];
#pragma unroll
                for (int i = 0; i < TM; i++) {
                    float av = (j == 0) ? aF[i].x : (j == 1) ? aF[i].y : (j == 2) ? aF[i].z : aF[i].w;
                    ull ap = pack_dup(av);
#pragma unroll
                    for (int c2 = 0; c2 < TN / 2; c2++)
                        acc[i][c2] = ffma2(ap, bp[c2], acc[i][c2]);
                }
            }
        }
        __syncthreads();
    }

#pragma unroll
    for (int i = 0; i < TM; i++) {
        int gr = rowBase + ty * TM + i;
        if (gr < N_NODES) {
            float4 o0, o1;
            ((ull*)&o0)[0] = acc[i][0];
            ((ull*)&o0)[1] = acc[i][1];
            ((ull*)&o1)[0] = acc[i][2];
            ((ull*)&o1)[1] = acc[i][3];
            *(float4*)&C[(size_t)gr * BN + tx * TN] = o0;
            *(float4*)&C[(size_t)gr * BN + tx * TN + 4] = o1;
        }
    }
}

// ---------------- aggregation + bias (+ relu + layernorm) -------------------
// One warp per node. COLS in {128,64}.
template <int COLS, bool RELU_LN>
__global__ void k_agg(const float* __restrict__ xw, const float* __restrict__ bias,
                      const float* __restrict__ gamma, const float* __restrict__ beta,
                      float* __restrict__ out) {
    int w = (blockIdx.x * blockDim.x + threadIdx.x) >> 5;
    int lane = threadIdx.x & 31;
    if (w >= N_NODES) return;
    constexpr int V = COLS / 32;  // 4 or 2
    float di = g_dinv[w];
    int beg = g_off[w], end = g_off[w + 1];

    float acc[V];
#pragma unroll
    for (int j = 0; j < V; j++) acc[j] = 0.f;

    int k = beg;
    for (; k + 2 <= end; k += 2) {
        int s0 = __ldg(&g_col[k]);
        int s1 = __ldg(&g_col[k + 1]);
        float w0 = __ldg(&g_dinv[s0]);
        float w1 = __ldg(&g_dinv[s1]);
        if (V == 4) {
            float4 v0 = __ldg((const float4*)(xw + (size_t)s0 * COLS) + lane);
            float4 v1 = __ldg((const float4*)(xw + (size_t)s1 * COLS) + lane);
            acc[0] += w0 * v0.x + w1 * v1.x;
            acc[1] += w0 * v0.y + w1 * v1.y;
            acc[2] += w0 * v0.z + w1 * v1.z;
            acc[3] += w0 * v0.w + w1 * v1.w;
        } else {
            float2 v0 = __ldg((const float2*)(xw + (size_t)s0 * COLS) + lane);
            float2 v1 = __ldg((const float2*)(xw + (size_t)s1 * COLS) + lane);
            acc[0] += w0 * v0.x + w1 * v1.x;
            acc[1] += w0 * v0.y + w1 * v1.y;
        }
    }
    if (k < end) {
        int s0 = __ldg(&g_col[k]);
        float w0 = __ldg(&g_dinv[s0]);
        if (V == 4) {
            float4 v0 = __ldg((const float4*)(xw + (size_t)s0 * COLS) + lane);
            acc[0] += w0 * v0.x; acc[1] += w0 * v0.y;
            acc[2] += w0 * v0.z; acc[3] += w0 * v0.w;
        } else {
            float2 v0 = __ldg((const float2*)(xw + (size_t)s0 * COLS) + lane);
            acc[0] += w0 * v0.x; acc[1] += w0 * v0.y;
        }
    }

    // self loop + scale + bias
    float di2 = di * di;
    float x[V];
    if (V == 4) {
        float4 vs = __ldg((const float4*)(xw + (size_t)w * COLS) + lane);
        x[0] = acc[0] * di + di2 * vs.x;
        x[1] = acc[1] * di + di2 * vs.y;
        x[2] = acc[2] * di + di2 * vs.z;
        x[3] = acc[3] * di + di2 * vs.w;
    } else {
        float2 vs = __ldg((const float2*)(xw + (size_t)w * COLS) + lane);
        x[0] = acc[0] * di + di2 * vs.x;
        x[1] = acc[1] * di + di2 * vs.y;
    }
#pragma unroll
    for (int j = 0; j < V; j++) x[j] += __ldg(&bias[lane * V + j]);

    if (RELU_LN) {
#pragma unroll
        for (int j = 0; j < V; j++) x[j] = fmaxf(x[j], 0.f);
        float s = 0.f, s2 = 0.f;
#pragma unroll
        for (int j = 0; j < V; j++) { s += x[j]; s2 += x[j] * x[j]; }
#pragma unroll
        for (int o = 16; o > 0; o >>= 1) {
            s += __shfl_xor_sync(0xFFFFFFFFu, s, o);
            s2 += __shfl_xor_sync(0xFFFFFFFFu, s2, o);
        }
        float mu = s * (1.0f / COLS);
        float var = s2 * (1.0f / COLS) - mu * mu;
        float inv = rsqrtf(var + EPS);
#pragma unroll
        for (int j = 0; j < V; j++)
            x[j] = (x[j] - mu) * inv * __ldg(&gamma[lane * V + j]) + __ldg(&beta[lane * V + j]);
    }

    if (V == 4) {
        float4 v = make_float4(x[0], x[1], x[2], x[3]);
        *((float4*)(out + (size_t)w * COLS) + lane) = v;
    } else {
        float2 v = make_float2(x[0], x[1]);
        *((float2*)(out + (size_t)w * COLS) + lane) = v;
    }
}

// ---------------- launch ----------------------------------------------------
extern "C" void kernel_launch(void* const* d_in, const int* in_sizes, int n_in,
                              void* d_out, int out_size) {
    const float* x  = (const float*)d_in[0];
    const void*  ei = d_in[1];
    const float* W1 = (const float*)d_in[2];
    const float* b1 = (const float*)d_in[3];
    const float* W2 = (const float*)d_in[4];
    const float* b2 = (const float*)d_in[5];
    const float* W3 = (const float*)d_in[6];
    const float* b3 = (const float*)d_in[7];
    const float* g1 = (const float*)d_in[8];
    const float* be1 = (const float*)d_in[9];
    const float* g2 = (const float*)d_in[10];
    const float* be2 = (const float*)d_in[11];
    float* out = (float*)d_out;
    int E = in_sizes[1] / 2;

    float *bufA, *bufB, *bufC;
    cudaGetSymbolAddress((void**)&bufA, g_bufA);
    cudaGetSymbolAddress((void**)&bufB, g_bufB);
    cudaGetSymbolAddress((void**)&bufC, g_bufC);

    int nb = (N_NODES + 1023) / 1024;  // 49

    k_init_detect<<<(N_NODES + 255) / 256, 256>>>((const int*)ei);
    k_degree<<<(E + 255) / 256, 256>>>(ei, E);
    k_scanA<<<nb, 1024>>>();
    k_scanB<<<1, 32>>>(nb);
    k_scanC<<<nb, 1024>>>();
    k_fill<<<(E + 255) / 256, 256>>>(ei, E);

    int gemmGrid = (N_NODES + 127) / 128;  // 391
    int aggGrid = (N_NODES + 7) / 8;       // 6250 blocks of 8 warps

    // layer 1
    k_gemm<128><<<gemmGrid, 256>>>(x, W1, bufA);
    k_agg<128, true><<<aggGrid, 256>>>(bufA, b1, g1, be1, bufB);
    // layer 2
    k_gemm<128><<<gemmGrid, 256>>>(bufB, W2, bufA);
    k_agg<128, true><<<aggGrid, 256>>>(bufA, b2, g2, be2, bufB);
    // layer 3 (no relu / no LN)
    k_gemm<64><<<gemmGrid, 128>>>(bufB, W3, bufC);
    k_agg<64, false><<<aggGrid, 256>>>(bufC, b3, nullptr, nullptr, out);
}

// round 6
// speedup vs baseline: 2.1329x; 2.1329x over previous
#include <cuda_runtime.h>
#include <cuda_bf16.h>
#include <cstddef>
#include <cstdint>

#define N_NODES 50000
#define D_H 128
#define D_OUT 64
#define MAX_E 800000
#define EPS 1e-5f

// ===================== scratch =============================================
__device__ float g_bufA[(size_t)N_NODES * D_H];
__device__ float g_bufB[(size_t)N_NODES * D_H];
__device__ float g_bufC[(size_t)N_NODES * D_OUT];
__device__ float g_dinv[N_NODES];
__device__ int   g_cnt[N_NODES];
__device__ int   g_cur[N_NODES];
__device__ int   g_off[N_NODES + 1];
__device__ int   g_col[MAX_E];
__device__ int   g_bsum[64];
__device__ int   g_nz;
// W images in mma B-fragment order: [hi: N*32 uint2][lo: N*32 uint2]
__device__ __align__(16) uint2 g_w1[2 * 128 * 32];
__device__ __align__(16) uint2 g_w2[2 * 128 * 32];
__device__ __align__(16) uint2 g_w3[2 * 64 * 32];

// ===================== preprocessing (validated) ============================
__global__ void k_init_detect(const int* __restrict__ p) {
    int i = blockIdx.x * blockDim.x + threadIdx.x;
    if (i < N_NODES) { g_cnt[i] = 0; g_cur[i] = 0; }
    if (i == 0) g_nz = 0;
    if (i < 1024) {
        if (p[2 * i + 1] != 0) atomicOr(&g_nz, 1);
    }
}
__device__ __forceinline__ int load_idx(const void* p, long long i, int is64) {
    return is64 ? (int)((const long long*)p)[i] : ((const int*)p)[i];
}
__global__ void k_degree(const void* __restrict__ idx, int E) {
    int e = blockIdx.x * blockDim.x + threadIdx.x;
    if (e >= E) return;
    int is64 = (g_nz == 0);
    int d = load_idx(idx, (long long)E + e, is64);
    atomicAdd(&g_cnt[d], 1);
}
__global__ void k_scanA() {
    __shared__ int s[1024];
    int i = blockIdx.x * 1024 + threadIdx.x;
    s[threadIdx.x] = (i < N_NODES) ? g_cnt[i] : 0;
    __syncthreads();
    for (int d = 512; d > 0; d >>= 1) {
        if (threadIdx.x < d) s[threadIdx.x] += s[threadIdx.x + d];
        __syncthreads();
    }
    if (threadIdx.x == 0) g_bsum[blockIdx.x] = s[0];
}
__global__ void k_scanB(int nb) {
    if (threadIdx.x == 0) {
        int run = 0;
        for (int b = 0; b < nb; b++) { int t = g_bsum[b]; g_bsum[b] = run; run += t; }
        g_off[N_NODES] = run;
    }
}
__global__ void k_scanC() {
    __shared__ int s[1024];
    int t = threadIdx.x;
    int i = blockIdx.x * 1024 + t;
    int v = (i < N_NODES) ? g_cnt[i] : 0;
    s[t] = v;
    __syncthreads();
    for (int d = 1; d < 1024; d <<= 1) {
        int x = (t >= d) ? s[t - d] : 0;
        __syncthreads();
        s[t] += x;
        __syncthreads();
    }
    if (i < N_NODES) {
        g_off[i] = g_bsum[blockIdx.x] + s[t] - v;
        g_dinv[i] = rsqrtf((float)v + 1.0f);
    }
}
__global__ void k_fill(const void* __restrict__ idx, int E) {
    int e = blockIdx.x * blockDim.x + threadIdx.x;
    if (e >= E) return;
    int is64 = (g_nz == 0);
    int s = load_idx(idx, e, is64);
    int d = load_idx(idx, (long long)E + e, is64);
    int pos = atomicAdd(&g_cur[d], 1);
    g_col[g_off[d] + pos] = s;
}

// ===================== bf16 split + mma helpers =============================
__device__ __forceinline__ void bsplit(float f, unsigned short& h, unsigned short& l) {
    __nv_bfloat16 bh = __float2bfloat16(f);
    float r = f - __bfloat162float(bh);
    __nv_bfloat16 bl = __float2bfloat16(r);
    h = __bfloat16_as_ushort(bh);
    l = __bfloat16_as_ushort(bl);
}

__device__ __forceinline__ void mma16816(float& d0, float& d1, float& d2, float& d3,
                                         uint32_t a0, uint32_t a1, uint32_t a2, uint32_t a3,
                                         uint32_t b0, uint32_t b1) {
    asm volatile(
        "mma.sync.aligned.m16n8k16.row.col.f32.bf16.bf16.f32 "
        "{%0,%1,%2,%3}, {%4,%5,%6,%7}, {%8,%9}, {%0,%1,%2,%3};"
        : "+f"(d0), "+f"(d1), "+f"(d2), "+f"(d3)
        : "r"(a0), "r"(a1), "r"(a2), "r"(a3), "r"(b0), "r"(b1));
}
__device__ __forceinline__ void ldm_x4(uint32_t& r0, uint32_t& r1, uint32_t& r2, uint32_t& r3,
                                       uint32_t addr) {
    asm volatile("ldmatrix.sync.aligned.m8n8.x4.shared.b16 {%0,%1,%2,%3}, [%4];"
                 : "=r"(r0), "=r"(r1), "=r"(r2), "=r"(r3) : "r"(addr));
}
__device__ __forceinline__ uint32_t smem_u32(const void* p) {
    uint32_t a;
    asm("{ .reg .u64 t; cvta.to.shared.u64 t, %1; cvt.u32.u64 %0, t; }"
        : "=r"(a) : "l"(p));
    return a;
}

// Pack W into mma B-fragment order.
// For each product p(hi/lo), ntile t (N/8), kstep s (8), lane l:
//   n = t*8 + l/4, k0 = s*16 + (l%4)*2
//   b0 = {W[k0][n], W[k0+1][n]}  b1 = {W[k0+8][n], W[k0+9][n]}
__global__ void k_prepW(const float* __restrict__ W1, const float* __restrict__ W2,
                        const float* __restrict__ W3) {
    int b = blockIdx.x;
    const float* W = (b == 0) ? W1 : (b == 1) ? W2 : W3;
    uint2* dst = (b == 0) ? g_w1 : (b == 1) ? g_w2 : g_w3;
    int N = (b == 2) ? 64 : 128;
    int perProd = N * 32;  // uint2 entries per product
    for (int e = threadIdx.x; e < 2 * perProd; e += blockDim.x) {
        int p = e / perProd;
        int rem = e % perProd;
        int ts = rem / 32;      // t*8 + s
        int l = rem % 32;
        int t = ts / 8, s = ts % 8;
        int n = t * 8 + (l >> 2);
        int k0 = s * 16 + (l & 3) * 2;
        unsigned short v[4];
        unsigned short h, lo16;
        int ks[4] = {k0, k0 + 1, k0 + 8, k0 + 9};
#pragma unroll
        for (int q = 0; q < 4; q++) {
            bsplit(W[ks[q] * N + n], h, lo16);
            v[q] = p ? lo16 : h;
        }
        uint2 out;
        out.x = (uint32_t)v[0] | ((uint32_t)v[1] << 16);
        out.y = (uint32_t)v[2] | ((uint32_t)v[3] << 16);
        dst[e] = out;
    }
}

// ===================== tensor-core GEMM (mma.sync) ==========================
// C[M,N] = A[M,128] @ W[128,N]; hi/lo split bf16, fp32 accumulate.
// CTA: 128 rows, 256 threads = 8 warps (4m x 2n). Warp tile 32 x N/2.
#define A_STRIDE 136  // bf16 elements per row (padded)
template <int N>
__global__ void __launch_bounds__(256, 2) k_gemm_mma(const float* __restrict__ A,
                                                     const uint2* __restrict__ wimg,
                                                     float* __restrict__ C) {
    extern __shared__ char smem[];
    // A hi at 0, A lo at 128*A_STRIDE*2
    constexpr int LO_OFF = 128 * A_STRIDE * 2;
    constexpr int NSUB = N / 16;  // n-subtiles per warp (8 or 4)

    int tid = threadIdx.x;
    int lane = tid & 31;
    int wid = tid >> 5;
    int wm = wid & 3;        // warp m index (0..3)
    int wn = wid >> 2;       // warp n index (0..1)
    int rowBase = blockIdx.x * 128;

    // ---- load + convert A tile into smem (hi/lo bf16) ----
    {
        int r = tid >> 1;
        int cb = (tid & 1) * 64;
        int gr = rowBase + r;
        bool ok = (gr < N_NODES);
        const float4* a4 = (const float4*)(A + (size_t)gr * 128 + cb);
        uint2* hiP = (uint2*)(smem + (r * A_STRIDE + cb) * 2);
        uint2* loP = (uint2*)(smem + LO_OFF + (r * A_STRIDE + cb) * 2);
#pragma unroll
        for (int j = 0; j < 16; j++) {
            float4 v = ok ? __ldg(a4 + j) : make_float4(0.f, 0.f, 0.f, 0.f);
            unsigned short h0, l0, h1, l1, h2, l2, h3, l3;
            bsplit(v.x, h0, l0);
            bsplit(v.y, h1, l1);
            bsplit(v.z, h2, l2);
            bsplit(v.w, h3, l3);
            uint2 hv, lv;
            hv.x = (uint32_t)h0 | ((uint32_t)h1 << 16);
            hv.y = (uint32_t)h2 | ((uint32_t)h3 << 16);
            lv.x = (uint32_t)l0 | ((uint32_t)l1 << 16);
            lv.y = (uint32_t)l2 | ((uint32_t)l3 << 16);
            hiP[j] = hv;
            loP[j] = lv;
        }
    }
    __syncthreads();

    uint32_t su = smem_u32(smem);
    const uint2* Bh = wimg;
    const uint2* Bl = wimg + N * 32;

    float acc[2][NSUB][4];
#pragma unroll
    for (int i = 0; i < 2; i++)
#pragma unroll
        for (int j = 0; j < NSUB; j++)
#pragma unroll
            for (int q = 0; q < 4; q++) acc[i][j][q] = 0.f;

    // ldmatrix lane addressing (A row-major m16k16 tile):
    // lanes 0-7: rows m0+0..7 col k0 ; 8-15: rows m0+8..15 col k0
    // 16-23: rows m0+0..7 col k0+8 ; 24-31: rows m0+8..15 col k0+8
    int lrow = (lane & 7) + ((lane >> 3) & 1) * 8;
    int lcol = (lane >> 4) * 8;

#pragma unroll
    for (int ks = 0; ks < 8; ks++) {
        int k0 = ks * 16;
        uint32_t ah[2][4], al[2][4];
#pragma unroll
        for (int i = 0; i < 2; i++) {
            int m0 = wm * 32 + i * 16;
            uint32_t off = (uint32_t)((m0 + lrow) * A_STRIDE + k0 + lcol) * 2;
            ldm_x4(ah[i][0], ah[i][1], ah[i][2], ah[i][3], su + off);
            ldm_x4(al[i][0], al[i][1], al[i][2], al[i][3], su + LO_OFF + off);
        }
#pragma unroll
        for (int j = 0; j < NSUB; j++) {
            int ntile = wn * NSUB + j;
            int bidx = (ntile * 8 + ks) * 32 + lane;
            uint2 bh = __ldg(&Bh[bidx]);
            uint2 bl = __ldg(&Bl[bidx]);
#pragma unroll
            for (int i = 0; i < 2; i++) {
                mma16816(acc[i][j][0], acc[i][j][1], acc[i][j][2], acc[i][j][3],
                         ah[i][0], ah[i][1], ah[i][2], ah[i][3], bh.x, bh.y);
                mma16816(acc[i][j][0], acc[i][j][1], acc[i][j][2], acc[i][j][3],
                         ah[i][0], ah[i][1], ah[i][2], ah[i][3], bl.x, bl.y);
                mma16816(acc[i][j][0], acc[i][j][1], acc[i][j][2], acc[i][j][3],
                         al[i][0], al[i][1], al[i][2], al[i][3], bh.x, bh.y);
            }
        }
    }

    // ---- epilogue: write accumulators ----
#pragma unroll
    for (int i = 0; i < 2; i++) {
        int r0 = rowBase + wm * 32 + i * 16 + (lane >> 2);
#pragma unroll
        for (int j = 0; j < NSUB; j++) {
            int col = wn * (N / 2) + j * 8 + (lane & 3) * 2;
            if (r0 < N_NODES)
                *(float2*)&C[(size_t)r0 * N + col] = make_float2(acc[i][j][0], acc[i][j][1]);
            if (r0 + 8 < N_NODES)
                *(float2*)&C[(size_t)(r0 + 8) * N + col] = make_float2(acc[i][j][2], acc[i][j][3]);
        }
    }
}

// ===================== aggregation (validated, unchanged) ===================
template <int COLS, bool RELU_LN>
__global__ void k_agg(const float* __restrict__ xw, const float* __restrict__ bias,
                      const float* __restrict__ gamma, const float* __restrict__ beta,
                      float* __restrict__ out) {
    int w = (blockIdx.x * blockDim.x + threadIdx.x) >> 5;
    int lane = threadIdx.x & 31;
    if (w >= N_NODES) return;
    constexpr int V = COLS / 32;
    float di = g_dinv[w];
    int beg = g_off[w], end = g_off[w + 1];

    float acc[V];
#pragma unroll
    for (int j = 0; j < V; j++) acc[j] = 0.f;

    int k = beg;
    for (; k + 2 <= end; k += 2) {
        int s0 = __ldg(&g_col[k]);
        int s1 = __ldg(&g_col[k + 1]);
        float w0 = __ldg(&g_dinv[s0]);
        float w1 = __ldg(&g_dinv[s1]);
        if (V == 4) {
            float4 v0 = __ldg((const float4*)(xw + (size_t)s0 * COLS) + lane);
            float4 v1 = __ldg((const float4*)(xw + (size_t)s1 * COLS) + lane);
            acc[0] += w0 * v0.x + w1 * v1.x;
            acc[1] += w0 * v0.y + w1 * v1.y;
            acc[2] += w0 * v0.z + w1 * v1.z;
            acc[3] += w0 * v0.w + w1 * v1.w;
        } else {
            float2 v0 = __ldg((const float2*)(xw + (size_t)s0 * COLS) + lane);
            float2 v1 = __ldg((const float2*)(xw + (size_t)s1 * COLS) + lane);
            acc[0] += w0 * v0.x + w1 * v1.x;
            acc[1] += w0 * v0.y + w1 * v1.y;
        }
    }
    if (k < end) {
        int s0 = __ldg(&g_col[k]);
        float w0 = __ldg(&g_dinv[s0]);
        if (V == 4) {
            float4 v0 = __ldg((const float4*)(xw + (size_t)s0 * COLS) + lane);
            acc[0] += w0 * v0.x; acc[1] += w0 * v0.y;
            acc[2] += w0 * v0.z; acc[3] += w0 * v0.w;
        } else {
            float2 v0 = __ldg((const float2*)(xw + (size_t)s0 * COLS) + lane);
            acc[0] += w0 * v0.x; acc[1] += w0 * v0.y;
        }
    }

    float di2 = di * di;
    float x[V];
    if (V == 4) {
        float4 vs = __ldg((const float4*)(xw + (size_t)w * COLS) + lane);
        x[0] = acc[0] * di + di2 * vs.x;
        x[1] = acc[1] * di + di2 * vs.y;
        x[2] = acc[2] * di + di2 * vs.z;
        x[3] = acc[3] * di + di2 * vs.w;
    } else {
        float2 vs = __ldg((const float2*)(xw + (size_t)w * COLS) + lane);
        x[0] = acc[0] * di + di2 * vs.x;
        x[1] = acc[1] * di + di2 * vs.y;
    }
#pragma unroll
    for (int j = 0; j < V; j++) x[j] += __ldg(&bias[lane * V + j]);

    if (RELU_LN) {
#pragma unroll
        for (int j = 0; j < V; j++) x[j] = fmaxf(x[j], 0.f);
        float s = 0.f, s2 = 0.f;
#pragma unroll
        for (int j = 0; j < V; j++) { s += x[j]; s2 += x[j] * x[j]; }
#pragma unroll
        for (int o = 16; o > 0; o >>= 1) {
            s += __shfl_xor_sync(0xFFFFFFFFu, s, o);
            s2 += __shfl_xor_sync(0xFFFFFFFFu, s2, o);
        }
        float mu = s * (1.0f / COLS);
        float var = s2 * (1.0f / COLS) - mu * mu;
        float inv = rsqrtf(var + EPS);
#pragma unroll
        for (int j = 0; j < V; j++)
            x[j] = (x[j] - mu) * inv * __ldg(&gamma[lane * V + j]) + __ldg(&beta[lane * V + j]);
    }

    if (V == 4) {
        float4 v = make_float4(x[0], x[1], x[2], x[3]);
        *((float4*)(out + (size_t)w * COLS) + lane) = v;
    } else {
        float2 v = make_float2(x[0], x[1]);
        *((float2*)(out + (size_t)w * COLS) + lane) = v;
    }
}

// ===================== launch ===============================================
extern "C" void kernel_launch(void* const* d_in, const int* in_sizes, int n_in,
                              void* d_out, int out_size) {
    const float* x  = (const float*)d_in[0];
    const void*  ei = d_in[1];
    const float* W1 = (const float*)d_in[2];
    const float* b1 = (const float*)d_in[3];
    const float* W2 = (const float*)d_in[4];
    const float* b2 = (const float*)d_in[5];
    const float* W3 = (const float*)d_in[6];
    const float* b3 = (const float*)d_in[7];
    const float* g1 = (const float*)d_in[8];
    const float* be1 = (const float*)d_in[9];
    const float* g2 = (const float*)d_in[10];
    const float* be2 = (const float*)d_in[11];
    float* out = (float*)d_out;
    int E = in_sizes[1] / 2;

    float *bufA, *bufB, *bufC;
    uint2 *w1i, *w2i, *w3i;
    cudaGetSymbolAddress((void**)&bufA, g_bufA);
    cudaGetSymbolAddress((void**)&bufB, g_bufB);
    cudaGetSymbolAddress((void**)&bufC, g_bufC);
    cudaGetSymbolAddress((void**)&w1i, g_w1);
    cudaGetSymbolAddress((void**)&w2i, g_w2);
    cudaGetSymbolAddress((void**)&w3i, g_w3);

    int smemA = 2 * 128 * A_STRIDE * 2;  // 69632 bytes (hi + lo)
    cudaFuncSetAttribute(k_gemm_mma<128>, cudaFuncAttributeMaxDynamicSharedMemorySize, smemA);
    cudaFuncSetAttribute(k_gemm_mma<64>,  cudaFuncAttributeMaxDynamicSharedMemorySize, smemA);

    int nb = (N_NODES + 1023) / 1024;  // 49

    k_prepW<<<3, 256>>>(W1, W2, W3);
    k_init_detect<<<(N_NODES + 255) / 256, 256>>>((const int*)ei);
    k_degree<<<(E + 255) / 256, 256>>>(ei, E);
    k_scanA<<<nb, 1024>>>();
    k_scanB<<<1, 32>>>(nb);
    k_scanC<<<nb, 1024>>>();
    k_fill<<<(E + 255) / 256, 256>>>(ei, E);

    int gemmGrid = (N_NODES + 127) / 128;  // 391
    int aggGrid = (N_NODES + 7) / 8;       // 6250

    // layer 1
    k_gemm_mma<128><<<gemmGrid, 256, smemA>>>(x, w1i, bufA);
    k_agg<128, true><<<aggGrid, 256>>>(bufA, b1, g1, be1, bufB);
    // layer 2
    k_gemm_mma<128><<<gemmGrid, 256, smemA>>>(bufB, w2i, bufA);
    k_agg<128, true><<<aggGrid, 256>>>(bufA, b2, g2, be2, bufB);
    // layer 3
    k_gemm_mma<64><<<gemmGrid, 256, smemA>>>(bufB, w3i, bufC);
    k_agg<64, false><<<aggGrid, 256>>>(bufC, b3, nullptr, nullptr, out);
}